// round 1
// baseline (speedup 1.0000x reference)
#include <cuda_runtime.h>

#define NNODES 10000
#define INF 128
#define OUTF 256
#define TM 64
#define TN 128
#define KT 32

// Scratch accumulator h[N, 128] — device global (no allocations allowed).
__device__ __align__(16) float g_h[NNODES * INF];

// ---------------------------------------------------------------------------
// Kernel 1: zero the accumulator (graph replays require re-zero every call).
// ---------------------------------------------------------------------------
__global__ void zero_h_kernel() {
    int i = blockIdx.x * blockDim.x + threadIdx.x;
    if (i < NNODES * INF / 4) {
        reinterpret_cast<float4*>(g_h)[i] = make_float4(0.f, 0.f, 0.f, 0.f);
    }
}

// ---------------------------------------------------------------------------
// Kernel 2: edge scatter. One warp per edge; each lane moves one float4
// (32 lanes x 4 floats = 128 features). red.global.add.v4.f32 = no-return
// vector atomic -> 4x fewer L2 atomic ops than scalar atomicAdd.
// feature (5MB) and g_h (5MB) both fit in L2.
// ---------------------------------------------------------------------------
__global__ void __launch_bounds__(256) scatter_kernel(
    const float* __restrict__ feature,
    const int* __restrict__ src,
    const int* __restrict__ dst,
    int n_edges)
{
    int gid  = blockIdx.x * blockDim.x + threadIdx.x;
    int e    = gid >> 5;
    int lane = gid & 31;
    if (e >= n_edges) return;

    int s = __ldg(src + e);
    int d = __ldg(dst + e);

    float4 v = __ldg(reinterpret_cast<const float4*>(feature) + s * (INF / 4) + lane);
    float4* dp = reinterpret_cast<float4*>(g_h) + d * (INF / 4) + lane;

    asm volatile("red.global.add.v4.f32 [%0], {%1, %2, %3, %4};"
                 :: "l"(dp), "f"(v.x), "f"(v.y), "f"(v.z), "f"(v.w)
                 : "memory");
}

// ---------------------------------------------------------------------------
// Kernel 3: out = h @ W + b.  Tiled SGEMM: block tile 64x128, K-tile 32,
// 256 threads, each thread computes a 4x8 micro-tile in registers.
// h tile stored transposed in smem so the inner-loop A read is one LDS.128.
// ---------------------------------------------------------------------------
__global__ void __launch_bounds__(256) gemm_kernel(
    const float* __restrict__ W,
    const float* __restrict__ b,
    float* __restrict__ out)
{
    __shared__ float sh_a[KT][TM];   // [k][m] (transposed h tile)
    __shared__ float sh_w[KT][TN];   // [k][n]

    int t  = threadIdx.x;
    int tx = t & 15;    // n direction (8 cols each)
    int ty = t >> 4;    // m direction (4 rows each)
    int m0 = blockIdx.x * TM;
    int n0 = blockIdx.y * TN;

    float acc[4][8];
#pragma unroll
    for (int r = 0; r < 4; r++)
#pragma unroll
        for (int c = 0; c < 8; c++) acc[r][c] = 0.f;

    for (int k0 = 0; k0 < INF; k0 += KT) {
        // Load h tile (64 rows x 32 k) as float4 along k, store transposed.
#pragma unroll
        for (int j = 0; j < 2; j++) {
            int idx = t + j * 256;         // 0..511 float4 slots
            int m   = idx >> 3;            // 8 float4 per row
            int k4  = idx & 7;
            float4 v = make_float4(0.f, 0.f, 0.f, 0.f);
            int gm = m0 + m;
            if (gm < NNODES)
                v = *reinterpret_cast<const float4*>(g_h + gm * INF + k0 + k4 * 4);
            sh_a[k4 * 4 + 0][m] = v.x;
            sh_a[k4 * 4 + 1][m] = v.y;
            sh_a[k4 * 4 + 2][m] = v.z;
            sh_a[k4 * 4 + 3][m] = v.w;
        }
        // Load W tile (32 k x 128 n), float4, direct.
#pragma unroll
        for (int j = 0; j < 4; j++) {
            int idx = t + j * 256;         // 0..1023 float4 slots
            int k   = idx >> 5;            // 32 float4 per row
            int n4  = idx & 31;
            float4 v = __ldg(reinterpret_cast<const float4*>(
                W + (size_t)(k0 + k) * OUTF + n0 + n4 * 4));
            *reinterpret_cast<float4*>(&sh_w[k][n4 * 4]) = v;
        }
        __syncthreads();

#pragma unroll
        for (int k = 0; k < KT; k++) {
            float4 av = *reinterpret_cast<const float4*>(&sh_a[k][ty * 4]);
            float4 w0 = *reinterpret_cast<const float4*>(&sh_w[k][tx * 8]);
            float4 w1 = *reinterpret_cast<const float4*>(&sh_w[k][tx * 8 + 4]);
            float a[4] = {av.x, av.y, av.z, av.w};
            float w[8] = {w0.x, w0.y, w0.z, w0.w, w1.x, w1.y, w1.z, w1.w};
#pragma unroll
            for (int r = 0; r < 4; r++)
#pragma unroll
                for (int c = 0; c < 8; c++)
                    acc[r][c] += a[r] * w[c];
        }
        __syncthreads();
    }

    // Epilogue: add bias, store (guard M edge: 10000 % 64 != 0).
    float4 b0 = __ldg(reinterpret_cast<const float4*>(b + n0 + tx * 8));
    float4 b1 = __ldg(reinterpret_cast<const float4*>(b + n0 + tx * 8 + 4));
#pragma unroll
    for (int r = 0; r < 4; r++) {
        int gm = m0 + ty * 4 + r;
        if (gm < NNODES) {
            float4 o0 = make_float4(acc[r][0] + b0.x, acc[r][1] + b0.y,
                                    acc[r][2] + b0.z, acc[r][3] + b0.w);
            float4 o1 = make_float4(acc[r][4] + b1.x, acc[r][5] + b1.y,
                                    acc[r][6] + b1.z, acc[r][7] + b1.w);
            float* op = out + (size_t)gm * OUTF + n0 + tx * 8;
            *reinterpret_cast<float4*>(op)     = o0;
            *reinterpret_cast<float4*>(op + 4) = o1;
        }
    }
}

// ---------------------------------------------------------------------------
extern "C" void kernel_launch(void* const* d_in, const int* in_sizes, int n_in,
                              void* d_out, int out_size) {
    const float* feature = (const float*)d_in[0];
    const int*   src     = (const int*)d_in[1];
    const int*   dst     = (const int*)d_in[2];
    const float* W       = (const float*)d_in[3];
    const float* b       = (const float*)d_in[4];
    float*       out     = (float*)d_out;

    int n_edges = in_sizes[1];

    // 1) zero accumulator
    int zn = NNODES * INF / 4;
    zero_h_kernel<<<(zn + 255) / 256, 256>>>();

    // 2) scatter: one warp per edge
    long long total_threads = (long long)n_edges * 32;
    int blocks = (int)((total_threads + 255) / 256);
    scatter_kernel<<<blocks, 256>>>(feature, src, dst, n_edges);

    // 3) GEMM + bias
    dim3 grid((NNODES + TM - 1) / TM, OUTF / TN);
    gemm_kernel<<<grid, 256>>>(W, b, out);
}